// round 16
// baseline (speedup 1.0000x reference)
#include <cuda_runtime.h>
#include <cuda_fp16.h>
#include <math.h>

#define BATCH 256
#define TOUT  36
#define SIN   96
#define SINP  128
#define DIM   1024
#define HID   1024
#define NLAY  2
#define NSPLIT 8

typedef __half f16;

#define BH      (BATCH * HID)
#define PAR     (2 * BH)
#define XOFF    ((size_t)BATCH * TOUT * DIM)
#define SROW    40

// ---------------- scratch ----------------
__device__ float g_h[NLAY * BATCH * HID];
__device__ f16   g_hd0[2 * BATCH * HID];
__device__ f16   g_hd1[2][2 * BATCH * HID];
__device__ f16   g_xd[2 * (size_t)BATCH * TOUT * DIM];
__device__ f16   g_xcd[2 * BATCH * DIM];
__device__ f16   g_wencd[2 * BATCH * HID];
__device__ f16   g_tmpd[2 * BATCH * DIM];
__device__ float g_attnP[NSPLIT * BATCH * SIN];
__device__ float g_gh0[BATCH * 3 * HID];
__device__ float g_gh1[BATCH * 3 * HID];
// single-fp16 weights
__device__ f16 g_attnWd[SINP * (DIM + HID)];
__device__ f16 g_combWd[DIM * (DIM + HID)];
__device__ f16 g_Wihd[NLAY * 3 * HID * DIM];
__device__ f16 g_Whhd[NLAY * 3 * HID * HID];
__device__ f16 g_out1d[DIM * HID];
__device__ f16 g_out2d[DIM * DIM];

// ---------------- helpers ----------------
__device__ __forceinline__ void dec2(float v, f16& hi, f16& lo) {
    hi = __float2half(v);
    lo = __float2half(v - __half2float(hi));
}

__device__ __forceinline__ void mma_f16(float c[4], const unsigned a[4], const unsigned b0, const unsigned b1) {
    asm volatile(
        "mma.sync.aligned.m16n8k16.row.col.f32.f16.f16.f32 "
        "{%0,%1,%2,%3},{%4,%5,%6,%7},{%8,%9},{%0,%1,%2,%3};\n"
        : "+f"(c[0]), "+f"(c[1]), "+f"(c[2]), "+f"(c[3])
        : "r"(a[0]), "r"(a[1]), "r"(a[2]), "r"(a[3]), "r"(b0), "r"(b1));
}

__device__ __forceinline__ void ldsm4(unsigned r[4], unsigned addr) {
    asm volatile("ldmatrix.sync.aligned.m8n8.x4.shared.b16 {%0,%1,%2,%3}, [%4];"
                 : "=r"(r[0]), "=r"(r[1]), "=r"(r[2]), "=r"(r[3]) : "r"(addr));
}

__device__ __forceinline__ void cpa16(unsigned dst, const void* src) {
    asm volatile("cp.async.cg.shared.global [%0], [%1], 16;" :: "r"(dst), "l"(src));
}

// ---------------- gemm argument bundle ----------------
struct GArg {
    const f16* A0; size_t aoff0; int lda0; int K0;
    const f16* A1; size_t aoff1; int lda1;
    const f16* Wd;
    const float* bias;
    float* C; int ldc;
    f16* Cd; size_t cdoff; int ldcd;
    int N; int K; int kw; int act;
};

// ---------------- generic tensor-core GEMM (BM=64,BN=64,BK=32) ------------
// A: fp16 hi/lo (lo at +aoff), W: single fp16. 2-term compensated MMA.
__device__ __forceinline__ void gemm_body(const GArg& g)
{
    __shared__ __align__(16) f16 As[2][2][64 * SROW];   // [buf][hi/lo]
    __shared__ __align__(16) f16 Ws[2][64 * SROW];      // [buf]

    const int tid = threadIdx.x, lane = tid & 31, warp = tid >> 5;
    const int wm = (warp >> 1) * 32, wn = (warp & 1) * 32;
    const int rowBase = blockIdx.y * 64, colBase = blockIdx.x * 64;

    const int r0c = tid >> 2, c0c = (tid & 3) * 8;
    const int r1c = (tid + 128) >> 2, c1c = c0c;

    float acc[2][4][4];
#pragma unroll
    for (int mt = 0; mt < 2; mt++)
#pragma unroll
        for (int nt = 0; nt < 4; nt++)
#pragma unroll
            for (int q = 0; q < 4; q++) acc[mt][nt][q] = 0.f;

    const int nsteps = g.K >> 5;

    auto prefetch = [&](int s, int buf) {
        int k0 = s << 5;
        const f16* Ab; size_t ao; int lda, kk;
        if (k0 < g.K0) { Ab = g.A0; ao = g.aoff0; lda = g.lda0; kk = k0; }
        else           { Ab = g.A1; ao = g.aoff1; lda = g.lda1; kk = k0 - g.K0; }
        {
            const f16* p0 = Ab + (size_t)(rowBase + r0c) * lda + kk + c0c;
            const f16* p1 = Ab + (size_t)(rowBase + r1c) * lda + kk + c1c;
            cpa16((unsigned)__cvta_generic_to_shared(&As[buf][0][r0c * SROW + c0c]), p0);
            cpa16((unsigned)__cvta_generic_to_shared(&As[buf][0][r1c * SROW + c1c]), p1);
            cpa16((unsigned)__cvta_generic_to_shared(&As[buf][1][r0c * SROW + c0c]), p0 + ao);
            cpa16((unsigned)__cvta_generic_to_shared(&As[buf][1][r1c * SROW + c1c]), p1 + ao);
        }
        {
            const f16* p0 = g.Wd + (size_t)(colBase + r0c) * g.kw + k0 + c0c;
            const f16* p1 = g.Wd + (size_t)(colBase + r1c) * g.kw + k0 + c1c;
            cpa16((unsigned)__cvta_generic_to_shared(&Ws[buf][r0c * SROW + c0c]), p0);
            cpa16((unsigned)__cvta_generic_to_shared(&Ws[buf][r1c * SROW + c1c]), p1);
        }
        asm volatile("cp.async.commit_group;");
    };

    prefetch(0, 0);

    const int aRow = lane & 15, aCol = (lane >> 4) << 3;
    const int bRow = ((lane >> 4) << 3) + (lane & 7), bCol = ((lane >> 3) & 1) << 3;

    for (int s = 0; s < nsteps; s++) {
        int buf = s & 1;
        if (s + 1 < nsteps) {
            prefetch(s + 1, buf ^ 1);
            asm volatile("cp.async.wait_group 1;");
        } else {
            asm volatile("cp.async.wait_group 0;");
        }
        __syncthreads();

#pragma unroll
        for (int h = 0; h < 2; h++) {
            int kk16 = h << 4;
            unsigned ah[2][4], al[2][4], bh[2][4];
#pragma unroll
            for (int mt = 0; mt < 2; mt++) {
                int ro = (wm + mt * 16 + aRow) * SROW + kk16 + aCol;
                ldsm4(ah[mt], (unsigned)__cvta_generic_to_shared(&As[buf][0][ro]));
                ldsm4(al[mt], (unsigned)__cvta_generic_to_shared(&As[buf][1][ro]));
            }
#pragma unroll
            for (int np = 0; np < 2; np++) {
                int ro = (wn + np * 16 + bRow) * SROW + kk16 + bCol;
                ldsm4(bh[np], (unsigned)__cvta_generic_to_shared(&Ws[buf][ro]));
            }
#pragma unroll
            for (int mt = 0; mt < 2; mt++)
#pragma unroll
                for (int nt = 0; nt < 4; nt++) {
                    int np = nt >> 1, q = (nt & 1) * 2;
                    mma_f16(acc[mt][nt], ah[mt], bh[np][q], bh[np][q + 1]);
                    mma_f16(acc[mt][nt], al[mt], bh[np][q], bh[np][q + 1]);
                }
        }
        __syncthreads();
    }

#pragma unroll
    for (int mt = 0; mt < 2; mt++)
#pragma unroll
        for (int nt = 0; nt < 4; nt++) {
            int r0 = rowBase + wm + mt * 16 + (lane >> 2);
            int c0 = colBase + wn + nt * 8 + (lane & 3) * 2;
            if (c0 >= g.N) continue;
            float b0 = g.bias ? g.bias[c0] : 0.f;
            float b1 = g.bias ? g.bias[c0 + 1] : 0.f;
#pragma unroll
            for (int p = 0; p < 2; p++) {
                int r = r0 + p * 8;
                float v0 = acc[mt][nt][p * 2] + b0;
                float v1 = acc[mt][nt][p * 2 + 1] + b1;
                if (g.act == 1) { v0 = fmaxf(v0, 0.f); v1 = fmaxf(v1, 0.f); }
                if (g.C) {
                    g.C[(size_t)r * g.ldc + c0] = v0;
                    g.C[(size_t)r * g.ldc + c0 + 1] = v1;
                }
                if (g.Cd) {
                    f16 h0, l0, h1, l1;
                    dec2(v0, h0, l0);
                    dec2(v1, h1, l1);
                    size_t o = (size_t)r * g.ldcd + c0;
                    g.Cd[o] = h0; g.Cd[o + 1] = h1;
                    g.Cd[g.cdoff + o] = l0; g.Cd[g.cdoff + o + 1] = l1;
                }
            }
        }
}

__global__ __launch_bounds__(128) void gemm_tc(GArg g)          { gemm_body(g); }
__global__ __launch_bounds__(128) void gemm_tc2(GArg a, GArg b) { gemm_body(blockIdx.z ? b : a); }

// split-K attention GEMM: blockIdx.z = split (K=256 each), partials to g.C
__global__ __launch_bounds__(128) void gemm_attnsp(GArg g)
{
    GArg l = g;
    int z = blockIdx.z;
    if (z < 4) { l.A0 = g.A0 + z * 256; l.aoff0 = g.aoff0; l.lda0 = g.lda0; }
    else       { l.A0 = g.A1 + (z - 4) * 256; l.aoff0 = g.aoff1; l.lda0 = g.lda1; }
    l.K0 = 256;
    l.K  = 256;
    l.Wd = g.Wd + z * 256;
    l.C  = g.C + (size_t)z * BATCH * SIN;
    l.bias = nullptr;
    gemm_body(l);
}

// ---------------- fused gi-GEMM + GRU gate (grouped-N) ---------------------
#define GSROW 40
#define GIGATE_SMEM ((2*2*32*GSROW + 2*3*64*GSROW) * (int)sizeof(f16))
__global__ __launch_bounds__(128) void gemm_gigate(
    const f16* __restrict__ A, size_t aoff, int lda,
    const f16* __restrict__ Wd,
    const float* __restrict__ bias,
    const float* __restrict__ gh,
    float* __restrict__ h, f16* __restrict__ hd, int K)
{
    extern __shared__ __align__(16) f16 dsm[];
    f16* AsB = dsm;                        // [buf][hl][32*GSROW]
    f16* WsB = dsm + 2 * 2 * 32 * GSROW;   // [buf][g][64*GSROW]

    const int tid = threadIdx.x, lane = tid & 31, warp = tid >> 5;
    const int wn = warp * 16;
    const int rowBase = blockIdx.y * 32, colBase = blockIdx.x * 64;

    float acc[3][2][2][4];
#pragma unroll
    for (int gg = 0; gg < 3; gg++)
#pragma unroll
        for (int mt = 0; mt < 2; mt++)
#pragma unroll
            for (int nt = 0; nt < 2; nt++)
#pragma unroll
                for (int q = 0; q < 4; q++) acc[gg][mt][nt][q] = 0.f;

    const int rA = tid >> 2, cA = (tid & 3) * 8;
    const int r1c = rA + 32;
    const int nsteps = K >> 5;

    auto As = [&](int buf, int hl) { return AsB + (buf * 2 + hl) * 32 * GSROW; };
    auto Ws = [&](int buf, int gg) { return WsB + (buf * 3 + gg) * 64 * GSROW; };

    auto prefetch = [&](int s, int buf) {
        int k0 = s << 5;
        const f16* pa = A + (size_t)(rowBase + rA) * lda + k0 + cA;
        cpa16((unsigned)__cvta_generic_to_shared(As(buf, 0) + rA * GSROW + cA), pa);
        cpa16((unsigned)__cvta_generic_to_shared(As(buf, 1) + rA * GSROW + cA), pa + aoff);
#pragma unroll
        for (int gg = 0; gg < 3; gg++) {
            const f16* p0 = Wd + (size_t)(gg * 1024 + colBase + rA) * K + k0 + cA;
            const f16* p1 = Wd + (size_t)(gg * 1024 + colBase + r1c) * K + k0 + cA;
            cpa16((unsigned)__cvta_generic_to_shared(Ws(buf, gg) + rA * GSROW + cA), p0);
            cpa16((unsigned)__cvta_generic_to_shared(Ws(buf, gg) + r1c * GSROW + cA), p1);
        }
        asm volatile("cp.async.commit_group;");
    };

    prefetch(0, 0);

    const int aRow = lane & 15, aCol = (lane >> 4) << 3;
    const int bRow = ((lane >> 4) << 3) + (lane & 7), bCol = ((lane >> 3) & 1) << 3;

    for (int s = 0; s < nsteps; s++) {
        int buf = s & 1;
        if (s + 1 < nsteps) {
            prefetch(s + 1, buf ^ 1);
            asm volatile("cp.async.wait_group 1;");
        } else {
            asm volatile("cp.async.wait_group 0;");
        }
        __syncthreads();

#pragma unroll
        for (int hh = 0; hh < 2; hh++) {
            int kk16 = hh << 4;
            unsigned ah[2][4], al[2][4], bh[3][4];
#pragma unroll
            for (int mt = 0; mt < 2; mt++) {
                int ro = (mt * 16 + aRow) * GSROW + kk16 + aCol;
                ldsm4(ah[mt], (unsigned)__cvta_generic_to_shared(As(buf, 0) + ro));
                ldsm4(al[mt], (unsigned)__cvta_generic_to_shared(As(buf, 1) + ro));
            }
#pragma unroll
            for (int gg = 0; gg < 3; gg++) {
                int ro = (wn + bRow) * GSROW + kk16 + bCol;
                ldsm4(bh[gg], (unsigned)__cvta_generic_to_shared(Ws(buf, gg) + ro));
            }
#pragma unroll
            for (int gg = 0; gg < 3; gg++)
#pragma unroll
                for (int mt = 0; mt < 2; mt++)
#pragma unroll
                    for (int nt = 0; nt < 2; nt++) {
                        int q = nt * 2;
                        mma_f16(acc[gg][mt][nt], ah[mt], bh[gg][q], bh[gg][q + 1]);
                        mma_f16(acc[gg][mt][nt], al[mt], bh[gg][q], bh[gg][q + 1]);
                    }
        }
        __syncthreads();
    }

#pragma unroll
    for (int mt = 0; mt < 2; mt++)
#pragma unroll
        for (int nt = 0; nt < 2; nt++) {
            int r0 = rowBase + mt * 16 + (lane >> 2);
            int c0 = colBase + wn + nt * 8 + (lane & 3) * 2;
#pragma unroll
            for (int p = 0; p < 2; p++) {
                int r = r0 + p * 8;
                const float* ghr = gh + (size_t)r * 3072;
#pragma unroll
                for (int cc = 0; cc < 2; cc++) {
                    int c = c0 + cc;
                    float ir  = acc[0][mt][nt][p * 2 + cc] + bias[c];
                    float iz  = acc[1][mt][nt][p * 2 + cc] + bias[1024 + c];
                    float in_ = acc[2][mt][nt][p * 2 + cc] + bias[2048 + c];
                    float hr = ghr[c], hz = ghr[1024 + c], hn = ghr[2048 + c];
                    float rg = 1.f / (1.f + expf(-(ir + hr)));
                    float zg = 1.f / (1.f + expf(-(iz + hz)));
                    float ng = tanhf(in_ + rg * hn);
                    int idx = r * 1024 + c;
                    float v = (1.f - zg) * ng + zg * h[idx];
                    h[idx] = v;
                    f16 hi, lo;
                    dec2(v, hi, lo);
                    hd[idx] = hi;
                    hd[BH + idx] = lo;
                }
            }
        }
}

// ---------------- decomposition / init ----------------
__global__ void decomp_kernel(const float* __restrict__ src, f16* __restrict__ dst,
                              size_t off, int n)
{
    int i = blockIdx.x * 256 + threadIdx.x;
    if (i < n) {
        f16 hi, lo;
        dec2(src[i], hi, lo);
        dst[i] = hi;
        dst[off + i] = lo;
    }
}

__global__ void decompW_kernel(const float* __restrict__ src, f16* __restrict__ dst, int n)
{
    int i = blockIdx.x * 256 + threadIdx.x;
    if (i < n) dst[i] = __float2half(src[i]);
}

__global__ void init_h_kernel(const float* __restrict__ hidden,
                              float* __restrict__ h,
                              f16* __restrict__ hd0, f16* __restrict__ hd1init)
{
    int i = blockIdx.x * 256 + threadIdx.x;
    float v = hidden[i];
    h[i] = v;
    int l = i >> 18;
    int j = i & (BH - 1);
    f16* hd = l ? hd1init : hd0;
    f16 hi, lo;
    dec2(v, hi, lo);
    hd[j] = hi;
    hd[BH + j] = lo;
}

__global__ void copy_kernel(const float* __restrict__ src, float* __restrict__ dst, int n)
{
    int i = blockIdx.x * 256 + threadIdx.x;
    if (i < n) dst[i] = src[i];
}

// ---------------- fused split-reduce + softmax + wenc ----------------
__global__ void softwenc_kernel(const float* __restrict__ part,
                                const float* __restrict__ attn_b,
                                const float* __restrict__ enc,
                                float* __restrict__ out_attn, int t,
                                f16* __restrict__ wencd)
{
    __shared__ float sm[256];
    __shared__ float a[SIN];
    int b = blockIdx.x, tid = threadIdx.x;
    float v = -1e30f;
    if (tid < SIN) {
        float s = attn_b[tid];
#pragma unroll
        for (int k = 0; k < NSPLIT; k++)
            s += part[(size_t)k * BATCH * SIN + b * SIN + tid];
        v = s;
    }
    sm[tid] = v; __syncthreads();
    for (int s = 128; s > 0; s >>= 1) {
        if (tid < s) sm[tid] = fmaxf(sm[tid], sm[tid + s]);
        __syncthreads();
    }
    float mx = sm[0]; __syncthreads();
    float e = (tid < SIN) ? expf(v - mx) : 0.f;
    sm[tid] = e; __syncthreads();
    for (int s = 128; s > 0; s >>= 1) {
        if (tid < s) sm[tid] += sm[tid + s];
        __syncthreads();
    }
    float inv = 1.f / sm[0];
    if (tid < SIN) {
        float aa = e * inv;
        a[tid] = aa;
        out_attn[(size_t)b * TOUT * SIN + (size_t)t * SIN + tid] = aa;
    }
    __syncthreads();

    const float4* ep = reinterpret_cast<const float4*>(enc + (size_t)b * SIN * HID) + tid;
    float ax = 0.f, ay = 0.f, az = 0.f, aww = 0.f;
#pragma unroll 4
    for (int s = 0; s < SIN; s++) {
        float4 vv = ep[(size_t)s * (HID / 4)];
        float w = a[s];
        ax = fmaf(w, vv.x, ax); ay = fmaf(w, vv.y, ay);
        az = fmaf(w, vv.z, az); aww = fmaf(w, vv.w, aww);
    }
    int idx = b * HID + tid * 4;
    float r4[4] = {ax, ay, az, aww};
#pragma unroll
    for (int q = 0; q < 4; q++) {
        f16 hi, lo;
        dec2(r4[q], hi, lo);
        wencd[idx + q] = hi;
        wencd[BH + idx + q] = lo;
    }
}

// ---------------- host orchestration ----------------
extern "C" void kernel_launch(void* const* d_in, const int* in_sizes, int n_in,
                              void* d_out, int out_size)
{
    const float* target = (const float*)d_in[0];
    const float* hidden = (const float*)d_in[1];
    const float* enc    = (const float*)d_in[2];
    const float* attn_W = (const float*)d_in[3];
    const float* attn_b = (const float*)d_in[4];
    const float* comb_W = (const float*)d_in[5];
    const float* comb_b = (const float*)d_in[6];
    const float* W_ih   = (const float*)d_in[7];
    const float* W_hh   = (const float*)d_in[8];
    const float* b_ih   = (const float*)d_in[9];
    const float* b_hh   = (const float*)d_in[10];
    const float* out1_W = (const float*)d_in[11];
    const float* out1_b = (const float*)d_in[12];
    const float* out2_W = (const float*)d_in[13];
    const float* out2_b = (const float*)d_in[14];

    float* out   = (float*)d_out;
    float* out_y = out;
    float* out_h = out + (size_t)BATCH * TOUT * DIM;
    float* out_a = out_h + (size_t)NLAY * BATCH * HID;

    float *h_, *attnP, *gh0b, *gh1b;
    f16 *hd0, *hd1, *xd, *xcd, *wencd, *tmpd;
    f16 *attnWd, *combWd, *Wihd, *Whhd, *out1d, *out2d;
    cudaGetSymbolAddress((void**)&h_,     g_h);
    cudaGetSymbolAddress((void**)&hd0,    g_hd0);
    cudaGetSymbolAddress((void**)&hd1,    g_hd1);
    cudaGetSymbolAddress((void**)&xd,     g_xd);
    cudaGetSymbolAddress((void**)&xcd,    g_xcd);
    cudaGetSymbolAddress((void**)&wencd,  g_wencd);
    cudaGetSymbolAddress((void**)&tmpd,   g_tmpd);
    cudaGetSymbolAddress((void**)&attnP,  g_attnP);
    cudaGetSymbolAddress((void**)&gh0b,   g_gh0);
    cudaGetSymbolAddress((void**)&gh1b,   g_gh1);
    cudaGetSymbolAddress((void**)&attnWd, g_attnWd);
    cudaGetSymbolAddress((void**)&combWd, g_combWd);
    cudaGetSymbolAddress((void**)&Wihd,   g_Wihd);
    cudaGetSymbolAddress((void**)&Whhd,   g_Whhd);
    cudaGetSymbolAddress((void**)&out1d,  g_out1d);
    cudaGetSymbolAddress((void**)&out2d,  g_out2d);

    static cudaStream_t s1 = nullptr, s2 = nullptr;
    static cudaEvent_t e_g1 = nullptr, e_gh = nullptr, e_done = nullptr, e_end = nullptr;
    if (!s1) {
        int pLeast, pGreatest;
        cudaDeviceGetStreamPriorityRange(&pLeast, &pGreatest);
        cudaStreamCreateWithPriority(&s1, cudaStreamNonBlocking, pGreatest);
        cudaStreamCreateWithPriority(&s2, cudaStreamNonBlocking, pLeast);
        cudaEventCreateWithFlags(&e_g1,   cudaEventDisableTiming);
        cudaEventCreateWithFlags(&e_gh,   cudaEventDisableTiming);
        cudaEventCreateWithFlags(&e_done, cudaEventDisableTiming);
        cudaEventCreateWithFlags(&e_end,  cudaEventDisableTiming);
        cudaFuncSetAttribute(gemm_gigate, cudaFuncAttributeMaxDynamicSharedMemorySize,
                             GIGATE_SMEM);
    }

    // prologue
    {
        int n;
        n = SIN * (DIM + HID);
        decompW_kernel<<<(n + 255) / 256, 256>>>(attn_W, attnWd, n);   // rows 96..127 stay 0
        n = DIM * (DIM + HID);
        decompW_kernel<<<(n + 255) / 256, 256>>>(comb_W, combWd, n);
        n = NLAY * 3 * HID * DIM;
        decompW_kernel<<<(n + 255) / 256, 256>>>(W_ih, Wihd, n);
        n = NLAY * 3 * HID * HID;
        decompW_kernel<<<(n + 255) / 256, 256>>>(W_hh, Whhd, n);
        n = DIM * HID;
        decompW_kernel<<<(n + 255) / 256, 256>>>(out1_W, out1d, n);
        n = DIM * DIM;
        decompW_kernel<<<(n + 255) / 256, 256>>>(out2_W, out2d, n);
        n = (int)(BATCH * TOUT * DIM);
        decomp_kernel<<<(n + 255) / 256, 256>>>(target, xd, XOFF, n);
        init_h_kernel<<<(NLAY * BH) / 256, 256>>>(hidden, h_, hd0, hd1 + PAR);
    }
    cudaEventRecord(e_g1, 0);
    cudaStreamWaitEvent(s1, e_g1, 0);

    const int LDX = TOUT * DIM;
    const size_t BD = (size_t)BATCH * DIM;

    for (int t = 0; t < TOUT; t++) {
        f16* hd1_rd = hd1 + ((t - 1) & 1) * (size_t)PAR;
        f16* hd1_wr = hd1 + (t & 1) * (size_t)PAR;
        const f16* xt = xd + (size_t)t * DIM;

        // ---- s2 (low prio): gh pair for step t, then out-head for t-1 ----
        cudaStreamWaitEvent(s2, e_g1, 0);
        GArg gh0a = { hd0, BH, HID, HID, nullptr, 0, 0,
                      Whhd, b_hh, gh0b, 3 * HID,
                      nullptr, 0, 0, 3 * HID, HID, HID, 0 };
        GArg gh1a = { hd1_rd, BH, HID, HID, nullptr, 0, 0,
                      Whhd + (size_t)3 * HID * HID, b_hh + 3 * HID,
                      gh1b, 3 * HID, nullptr, 0, 0, 3 * HID, HID, HID, 0 };
        gemm_tc2<<<dim3(48, 4, 2), 128, 0, s2>>>(gh0a, gh1a);
        cudaEventRecord(e_gh, s2);
        if (t > 0) {
            f16* hprev = hd1 + ((t - 1) & 1) * (size_t)PAR;
            GArg go1 = { hprev, BH, HID, HID, nullptr, 0, 0,
                         out1d, out1_b,
                         nullptr, 0, tmpd, BD, DIM, DIM, HID, HID, 0 };
            gemm_tc<<<dim3(16, 4), 128, 0, s2>>>(go1);
            GArg go2 = { tmpd, BD, DIM, DIM, nullptr, 0, 0,
                         out2d, out2_b,
                         out_y + (size_t)(t - 1) * DIM, LDX,
                         nullptr, 0, 0, DIM, DIM, DIM, 0 };
            gemm_tc<<<dim3(16, 4), 128, 0, s2>>>(go2);
        }

        // ---- s1 (high prio): attn(split-K) -> softwenc -> comb -> gigate x2
        GArg ga = { xt, XOFF, LDX, DIM, hd1_rd, BH, HID,
                    attnWd, nullptr,
                    attnP, SIN, nullptr, 0, 0, SIN, DIM + HID, DIM + HID, 0 };
        gemm_attnsp<<<dim3(2, 4, NSPLIT), 128, 0, s1>>>(ga);
        softwenc_kernel<<<BATCH, 256, 0, s1>>>(attnP, attn_b, enc, out_a, t, wencd);

        GArg gc = { xt, XOFF, LDX, DIM, wencd, BH, HID,
                    combWd, comb_b,
                    nullptr, 0, xcd, BD, DIM, DIM, DIM + HID, DIM + HID, 1 };
        gemm_tc<<<dim3(16, 4), 128, 0, s1>>>(gc);

        cudaStreamWaitEvent(s1, e_gh, 0);
        gemm_gigate<<<dim3(16, 8), 128, GIGATE_SMEM, s1>>>(
            xcd, BD, DIM, Wihd, b_ih, gh0b, h_, hd0, DIM);
        gemm_gigate<<<dim3(16, 8), 128, GIGATE_SMEM, s1>>>(
            hd0, BH, HID, Wihd + (size_t)3 * HID * DIM,
            b_ih + 3 * HID, gh1b, h_ + BH, hd1_wr, HID);
        cudaEventRecord(e_g1, s1);
    }

    // tail: out-head for t=35 on s2, join via s1, final hidden copy
    cudaStreamWaitEvent(s2, e_g1, 0);
    {
        f16* hlast = hd1 + ((TOUT - 1) & 1) * (size_t)PAR;
        GArg go1 = { hlast, BH, HID, HID, nullptr, 0, 0,
                     out1d, out1_b,
                     nullptr, 0, tmpd, BD, DIM, DIM, HID, HID, 0 };
        gemm_tc<<<dim3(16, 4), 128, 0, s2>>>(go1);
        GArg go2 = { tmpd, BD, DIM, DIM, nullptr, 0, 0,
                     out2d, out2_b,
                     out_y + (size_t)(TOUT - 1) * DIM, LDX,
                     nullptr, 0, 0, DIM, DIM, DIM, 0 };
        gemm_tc<<<dim3(16, 4), 128, 0, s2>>>(go2);
    }
    cudaEventRecord(e_done, s2);
    cudaStreamWaitEvent(s1, e_done, 0);
    copy_kernel<<<(NLAY * BH) / 256, 256, 0, s1>>>(h_, out_h, NLAY * BH);
    cudaEventRecord(e_end, s1);
    cudaStreamWaitEvent(0, e_end, 0);
}